// round 16
// baseline (speedup 1.0000x reference)
#include <cuda_runtime.h>

// CompetingRiskTabMLoss: Cox PH partial likelihood (Breslow, K causes) + CE, blended.
// Bucket-major pipeline: staged pass A (fused scatter), NB=32768 small buckets,
// warp-per-bucket events with register accumulation. Proven numerics (fp64 log).

#define KC 4
#define NCLS 5
#define NB 32768             // duration buckets (durations ~ U[0,1))
#define CAPB 64              // slots per bucket (Poisson(30.5) + ~6 sigma)
#define NPART 256            // scan partitions
#define BPP (NB / NPART)     // 128 buckets per partition
#define TPB 256
#define EPS 1e-8
#define ALPHA 0.4

struct __align__(32) Elem {  // 32B = one sector
    float dur, f0, f1, f2;   // f = exp(clipped eta)
    float f3, cause_bits, eta_own, pad;
};

// ---- scratch (no allocations allowed) ----
__device__ Elem   g_elem[(size_t)NB * CAPB];   // 64 MB bucket-major
__device__ Elem   g_ovf[4096];                 // overflow list (normally empty)
__device__ int    g_ovfb[4096];
__device__ int    g_cnt[NB];
__device__ int    g_ovf_cnt;
__device__ double g_bsum[NB * KC];
__device__ double g_sufx[NB * KC];
__device__ double g_part_sum[KC * NPART];
__device__ double g_part_sufx[KC * NPART];
__device__ double g_evsum[KC];
__device__ double g_evcnt[KC];
__device__ double g_ce;

// ---------------------------------------------------------------- helpers
__device__ __forceinline__ int bucket_of(float d) {
    int b = (int)(d * (float)NB);
    return b < 0 ? 0 : (b > NB - 1 ? NB - 1 : b);
}
__device__ __forceinline__ double warp_redd(double v) {
    #pragma unroll
    for (int o = 16; o; o >>= 1) v += __shfl_down_sync(0xffffffffu, v, o);
    return v;   // full sum valid in lane 0 ONLY
}
__device__ __forceinline__ float elem_f(const float4& a, const float4& q, int c) {
    return (c == 0) ? a.y : (c == 1) ? a.z : (c == 2) ? a.w : q.x;
}

// ---------------------------------------------------------------- init + nops
__global__ void k_init() {
    int i = blockIdx.x * blockDim.x + threadIdx.x;
    if (i < NB) g_cnt[i] = 0;
    if (i < KC * NPART) g_part_sum[i] = 0.0;
    if (i < KC) { g_evsum[i] = 0.0; g_evcnt[i] = 0.0; }
    if (i == 0) { g_ce = 0.0; g_ovf_cnt = 0; }
}
__global__ void k_nop() {}   // spacer so ncu (launch #4) captures k_passA

// ---------------------------------------------------------------- pass A (staged, fused scatter)
__global__ void __launch_bounds__(TPB) k_passA(const float* __restrict__ log_h,
                        const float* __restrict__ logits,
                        const float* __restrict__ dur,
                        const int*   __restrict__ et,
                        const int*   __restrict__ labels,
                        int n, int M) {
    __shared__ float4 sh4[TPB * 11];
    __shared__ double s_ce;
    int t = threadIdx.x;
    if (t == 0) s_ce = 0.0;

    int blockBase = blockIdx.x * TPB;
    int cnt = n - blockBase; if (cnt > TPB) cnt = TPB;
    int i = blockBase + t;
    bool staged = (M == 8);
    float inv = 1.0f / (float)M;

    // ---- stage log_h (coalesced) -> shared, then row-sum from shared ----
    if (staged) {
        int nf4 = cnt * 8;
        const float4* src = reinterpret_cast<const float4*>(log_h) + (size_t)blockBase * 8;
        for (int j = t; j < nf4; j += TPB) sh4[(j >> 3) * 9 + (j & 7)] = src[j];
    }
    __syncthreads();
    if (t < cnt) {
        float sx, sy, sz, sw_;
        sx = sy = sz = sw_ = 0.f;
        if (staged) {
            #pragma unroll
            for (int m = 0; m < 8; m++) {
                float4 v = sh4[t * 9 + m];
                sx += v.x; sy += v.y; sz += v.z; sw_ += v.w;
            }
        } else {
            const float4* lh = reinterpret_cast<const float4*>(log_h) + (size_t)i * M;
            for (int m = 0; m < M; m++) {
                float4 v = lh[m];
                sx += v.x; sy += v.y; sz += v.z; sw_ += v.w;
            }
        }
        float e0 = fminf(fmaxf(sx * inv, -50.f), 50.f);
        float e1 = fminf(fmaxf(sy * inv, -50.f), 50.f);
        float e2 = fminf(fmaxf(sz * inv, -50.f), 50.f);
        float e3 = fminf(fmaxf(sw_ * inv, -50.f), 50.f);

        float d = dur[i];
        int cause = et[i];
        float eta_own = (cause == 1) ? e0 : (cause == 2) ? e1 : (cause == 3) ? e2
                       : (cause == 4) ? e3 : 0.f;
        int b = bucket_of(d);
        int pos = atomicAdd(&g_cnt[b], 1);
        float4 pa = make_float4(d, expf(e0), expf(e1), expf(e2));
        float4 pq = make_float4(expf(e3), __int_as_float(cause), eta_own, 0.f);
        if (pos < CAPB) {
            float4* p = reinterpret_cast<float4*>(&g_elem[(size_t)b * CAPB + pos]);
            p[0] = pa; p[1] = pq;
        } else {
            int oi = atomicAdd(&g_ovf_cnt, 1);
            float4* p = reinterpret_cast<float4*>(&g_ovf[oi]);
            p[0] = pa; p[1] = pq;
            g_ovfb[oi] = b;
        }
    }
    __syncthreads();

    // ---- stage logits (coalesced) -> shared, CE with max-subtraction ----
    if (staged) {
        int nf4 = cnt * 10;
        const float4* src = reinterpret_cast<const float4*>(logits) + (size_t)blockBase * 10;
        for (int j = t; j < nf4; j += TPB) {
            int l = j / 10, r = j - l * 10;
            sh4[l * 11 + r] = src[j];
        }
    }
    __syncthreads();

    double ce = 0.0;
    if (t < cnt) {
        float lm[NCLS];
        #pragma unroll
        for (int j = 0; j < NCLS; j++) lm[j] = 0.f;
        if (staged) {
            #pragma unroll
            for (int j = 0; j < 10; j++) {
                float4 v = sh4[t * 11 + j];
                int base = j * 4;
                lm[(base + 0) % NCLS] += v.x;
                lm[(base + 1) % NCLS] += v.y;
                lm[(base + 2) % NCLS] += v.z;
                lm[(base + 3) % NCLS] += v.w;
            }
        } else {
            const float* lg = logits + (size_t)i * M * NCLS;
            for (int q = 0; q < M * NCLS; q++) lm[q % NCLS] += lg[q];
        }
        float mj[NCLS], mx = -3.4e38f;
        #pragma unroll
        for (int j = 0; j < NCLS; j++) { mj[j] = lm[j] * inv; mx = fmaxf(mx, mj[j]); }
        float se = 0.f;
        #pragma unroll
        for (int j = 0; j < NCLS; j++) se += expf(mj[j] - mx);
        ce = (double)(mx + logf(se) - mj[labels[i]]);
    }
    double v = warp_redd(ce);
    if ((t & 31) == 0 && v != 0.0) atomicAdd(&s_ce, v);
    __syncthreads();
    if (t == 0 && s_ce != 0.0) atomicAdd(&g_ce, s_ce);
}

// ---------------------------------------------------------------- bucket sums (warp-per-bucket loop)
// NOTE: warp_redd's full sum is valid in lane 0 ONLY -> lane 0 writes ALL four causes.
__global__ void __launch_bounds__(256) k_bsum() {
    int t = threadIdx.x;
    int w = t >> 5, lane = t & 31;
    int nov = g_ovf_cnt;                       // normally 0
    for (int b = blockIdx.x * 8 + w; b < NB; b += gridDim.x * 8) {
        int m = min(g_cnt[b], CAPB);
        double a0 = 0, a1 = 0, a2 = 0, a3 = 0;
        #pragma unroll
        for (int r = 0; r < 2; r++) {
            int j = lane + r * 32;
            if (j < m) {
                const float4* p = reinterpret_cast<const float4*>(&g_elem[(size_t)b * CAPB + j]);
                float4 a = p[0], q = p[1];
                a0 += a.y; a1 += a.z; a2 += a.w; a3 += q.x;
            }
        }
        a0 = warp_redd(a0); a1 = warp_redd(a1); a2 = warp_redd(a2); a3 = warp_redd(a3);
        if (lane == 0) {
            double s[KC] = {a0, a1, a2, a3};
            for (int j = 0; j < nov; j++) {     // fold overflow (normally empty)
                if (g_ovfb[j] == b) {
                    const float4* p = reinterpret_cast<const float4*>(&g_ovf[j]);
                    float4 a = p[0], q = p[1];
                    #pragma unroll
                    for (int c = 0; c < KC; c++) s[c] += (double)elem_f(a, q, c);
                }
            }
            #pragma unroll
            for (int c = 0; c < KC; c++) {
                g_bsum[b * KC + c] = s[c];
                atomicAdd(&g_part_sum[c * NPART + b / BPP], s[c]);
            }
        }
    }
}

// ---------------------------------------------------------------- suffix over parts (1 block)
__global__ void __launch_bounds__(NPART) k_sufB() {
    __shared__ double sd[NPART];
    int t = threadIdx.x;
    for (int c = 0; c < KC; c++) {
        double own = g_part_sum[c * NPART + t];
        sd[t] = own;
        __syncthreads();
        for (int off = 1; off < NPART; off <<= 1) {
            double v = (t + off < NPART) ? sd[t + off] : 0.0;
            __syncthreads();
            sd[t] += v;
            __syncthreads();
        }
        g_part_sufx[c * NPART + t] = sd[t] - own;  // exclusive suffix over parts
        __syncthreads();
    }
}

// ---------------------------------------------------------------- within-part suffix fixup
__global__ void __launch_bounds__(BPP) k_sufC() {
    __shared__ double sd[BPP];
    int t = threadIdx.x, p = blockIdx.x;
    int b = p * BPP + t;
    for (int c = 0; c < KC; c++) {
        double own = g_bsum[b * KC + c];
        sd[t] = own;
        __syncthreads();
        for (int off = 1; off < BPP; off <<= 1) {
            double v = (t + off < BPP) ? sd[t + off] : 0.0;
            __syncthreads();
            sd[t] += v;
            __syncthreads();
        }
        g_sufx[b * KC + c] = g_part_sufx[c * NPART + p] + sd[t] - own;
        __syncthreads();
    }
}

// ---------------------------------------------------------------- events (warp-per-bucket loop)
__global__ void __launch_bounds__(256) k_events() {
    __shared__ float  sh_dur[8][CAPB];
    __shared__ float  sh_f[8][KC][CAPB];
    __shared__ float  sh_eo[8][CAPB];
    __shared__ int    sh_c[8][CAPB];
    __shared__ double s_sum[KC];
    __shared__ double s_cnt[KC];

    int t = threadIdx.x;
    int w = t >> 5, lane = t & 31;
    if (t < KC) { s_sum[t] = 0.0; s_cnt[t] = 0.0; }
    __syncthreads();

    int nov_all = g_ovf_cnt;
    double acc_sum[KC] = {0.0, 0.0, 0.0, 0.0};
    int    acc_cnt[KC] = {0, 0, 0, 0};

    for (int b = blockIdx.x * 8 + w; b < NB; b += gridDim.x * 8) {
        int cnt = g_cnt[b];
        int m = min(cnt, CAPB);
        if (m == 0) continue;
        int nov = (cnt > CAPB) ? nov_all : 0;

        for (int j = lane; j < m; j += 32) {
            const float4* p = reinterpret_cast<const float4*>(&g_elem[(size_t)b * CAPB + j]);
            float4 a = p[0], q = p[1];
            sh_dur[w][j]  = a.x;
            sh_f[w][0][j] = a.y;
            sh_f[w][1][j] = a.z;
            sh_f[w][2][j] = a.w;
            sh_f[w][3][j] = q.x;
            sh_eo[w][j]   = q.z;
            sh_c[w][j]    = __float_as_int(q.y);
        }
        __syncwarp();

        #pragma unroll
        for (int r = 0; r < 2; r++) {
            int j = lane + r * 32;
            if (j < m) {
                int cv = sh_c[w][j];
                if (cv > 0) {
                    int cc = cv - 1;
                    float d_e = sh_dur[w][j];
                    const float* fp = sh_f[w][cc];
                    float acc = 0.f;
                    for (int j2 = 0; j2 < m; j2++)
                        acc += (sh_dur[w][j2] >= d_e) ? fp[j2] : 0.f;
                    for (int j2 = 0; j2 < nov; j2++) {   // same-bucket overflow elems
                        if (g_ovfb[j2] == b) {
                            const float4* p = reinterpret_cast<const float4*>(&g_ovf[j2]);
                            float4 a = p[0], q = p[1];
                            acc += (a.x >= d_e) ? elem_f(a, q, cc) : 0.f;
                        }
                    }
                    double denom = g_sufx[b * KC + cc] + (double)acc;
                    acc_sum[cc] += (double)sh_eo[w][j] - log(denom + EPS);
                    acc_cnt[cc] += 1;
                }
            }
        }
        __syncwarp();
    }

    #pragma unroll
    for (int c = 0; c < KC; c++) {
        double v = warp_redd(acc_sum[c]);
        double k = warp_redd((double)acc_cnt[c]);
        if (lane == 0 && k != 0.0) {
            atomicAdd(&s_sum[c], v);
            atomicAdd(&s_cnt[c], k);
        }
    }
    __syncthreads();
    if (t < KC && s_cnt[t] != 0.0) {
        atomicAdd(&g_evsum[t], s_sum[t]);
        atomicAdd(&g_evcnt[t], s_cnt[t]);
    }
}

// ---------------------------------------------------------------- finalize (+ overflow events)
__global__ void k_fin(float* __restrict__ out, int n) {
    double esum[KC], ecnt[KC];
    #pragma unroll
    for (int c = 0; c < KC; c++) { esum[c] = g_evsum[c]; ecnt[c] = g_evcnt[c]; }

    int nov = g_ovf_cnt;  // normally 0
    for (int i = 0; i < nov; i++) {
        const float4* p = reinterpret_cast<const float4*>(&g_ovf[i]);
        float4 a = p[0], q = p[1];
        int cv = __float_as_int(q.y);
        if (cv <= 0) continue;
        int cc = cv - 1, b = g_ovfb[i];
        float d_e = a.x;
        float acc = 0.f;
        int m = min(g_cnt[b], CAPB);
        for (int j = 0; j < m; j++) {
            const float4* pj = reinterpret_cast<const float4*>(&g_elem[(size_t)b * CAPB + j]);
            float4 aj = pj[0], qj = pj[1];
            acc += (aj.x >= d_e) ? elem_f(aj, qj, cc) : 0.f;
        }
        for (int j = 0; j < nov; j++) {
            if (g_ovfb[j] == b) {
                const float4* pj = reinterpret_cast<const float4*>(&g_ovf[j]);
                float4 aj = pj[0], qj = pj[1];
                acc += (aj.x >= d_e) ? elem_f(aj, qj, cc) : 0.f;
            }
        }
        double denom = g_sufx[b * KC + cc] + (double)acc;
        esum[cc] += (double)q.z - log(denom + EPS);
        ecnt[cc] += 1.0;
    }

    double ls = 0.0;
    #pragma unroll
    for (int c = 0; c < KC; c++) ls += -esum[c] / (ecnt[c] + EPS);
    double lc = g_ce / (double)n;
    out[0] = (float)(ALPHA * ls + (1.0 - ALPHA) * lc);
}

// ---------------------------------------------------------------- launch
extern "C" void kernel_launch(void* const* d_in, const int* in_sizes, int n_in,
                              void* d_out, int out_size) {
    const float* log_h  = (const float*)d_in[0];
    const float* logits = (const float*)d_in[1];
    const float* dur    = (const float*)d_in[2];
    const int*   et     = (const int*)d_in[3];
    const int*   labels = (const int*)d_in[4];
    float* out = (float*)d_out;

    int n = in_sizes[2];
    int M = in_sizes[0] / (n * KC);

    int nb = (n + TPB - 1) / TPB;

    k_init<<<(NB + TPB - 1) / TPB, TPB>>>();
    k_nop<<<1, 32>>>();                         // spacers: put k_passA at launch #4
    k_nop<<<1, 32>>>();                         // (ncu -s5 -c1 lands there)
    k_passA<<<nb, TPB>>>(log_h, logits, dur, et, labels, n, M);
    k_bsum<<<512, 256>>>();
    k_sufB<<<1, NPART>>>();
    k_sufC<<<NPART, BPP>>>();
    k_events<<<512, 256>>>();
    k_fin<<<1, 1>>>(out, n);
}

// round 17
// speedup vs baseline: 1.4834x; 1.4834x over previous
#include <cuda_runtime.h>

// CompetingRiskTabMLoss: Cox PH partial likelihood (Breslow, K causes) + CE, blended.
// Bucket-major pipeline: staged pass A (fused scatter), NB=32768 small buckets,
// warp-per-bucket events. fp32 transcendentals (fp64 only for suffix cumsums).

#define KC 4
#define NCLS 5
#define NB 32768             // duration buckets (durations ~ U[0,1))
#define CAPB 64              // slots per bucket (Poisson(30.5) + ~6 sigma)
#define NPART 256            // scan partitions
#define BPP (NB / NPART)     // 128 buckets per partition
#define TPB 256
#define EPS 1e-8
#define ALPHA 0.4

struct __align__(32) Elem {  // 32B = one sector
    float dur, f0, f1, f2;   // f = exp(clipped eta)
    float f3, cause_bits, eta_own, pad;
};

// ---- scratch (no allocations allowed) ----
__device__ Elem   g_elem[(size_t)NB * CAPB];   // 64 MB bucket-major
__device__ Elem   g_ovf[4096];                 // overflow list (normally empty)
__device__ int    g_ovfb[4096];
__device__ int    g_cnt[NB];
__device__ int    g_ovf_cnt;
__device__ double g_bsum[NB * KC];
__device__ double g_sufx[NB * KC];
__device__ double g_part_sum[KC * NPART];
__device__ double g_part_sufx[KC * NPART];
__device__ double g_evsum[KC];
__device__ double g_evcnt[KC];
__device__ double g_ce;

// ---------------------------------------------------------------- helpers
__device__ __forceinline__ int bucket_of(float d) {
    int b = (int)(d * (float)NB);
    return b < 0 ? 0 : (b > NB - 1 ? NB - 1 : b);
}
__device__ __forceinline__ double warp_redd(double v) {
    #pragma unroll
    for (int o = 16; o; o >>= 1) v += __shfl_down_sync(0xffffffffu, v, o);
    return v;   // full sum valid in lane 0 ONLY
}
__device__ __forceinline__ float warp_redf(float v) {
    #pragma unroll
    for (int o = 16; o; o >>= 1) v += __shfl_down_sync(0xffffffffu, v, o);
    return v;   // full sum valid in lane 0 ONLY
}
__device__ __forceinline__ float elem_f(const float4& a, const float4& q, int c) {
    return (c == 0) ? a.y : (c == 1) ? a.z : (c == 2) ? a.w : q.x;
}

// ---------------------------------------------------------------- init + nop
__global__ void k_init() {
    int i = blockIdx.x * blockDim.x + threadIdx.x;
    if (i < NB) g_cnt[i] = 0;
    if (i < KC * NPART) g_part_sum[i] = 0.0;
    if (i < KC) { g_evsum[i] = 0.0; g_evcnt[i] = 0.0; }
    if (i == 0) { g_ce = 0.0; g_ovf_cnt = 0; }
}
__global__ void k_nop() {}   // spacer: puts k_bsum at launch #4 for ncu

// ---------------------------------------------------------------- pass A (staged, fused scatter)
__global__ void __launch_bounds__(TPB) k_passA(const float* __restrict__ log_h,
                        const float* __restrict__ logits,
                        const float* __restrict__ dur,
                        const int*   __restrict__ et,
                        const int*   __restrict__ labels,
                        int n, int M) {
    __shared__ float4 sh4[TPB * 11];
    __shared__ double s_ce;
    int t = threadIdx.x;
    if (t == 0) s_ce = 0.0;

    int blockBase = blockIdx.x * TPB;
    int cnt = n - blockBase; if (cnt > TPB) cnt = TPB;
    int i = blockBase + t;
    bool staged = (M == 8);
    float inv = 1.0f / (float)M;

    // ---- stage log_h (coalesced) -> shared, then row-sum from shared ----
    if (staged) {
        int nf4 = cnt * 8;
        const float4* src = reinterpret_cast<const float4*>(log_h) + (size_t)blockBase * 8;
        for (int j = t; j < nf4; j += TPB) sh4[(j >> 3) * 9 + (j & 7)] = src[j];
    }
    __syncthreads();
    if (t < cnt) {
        float sx, sy, sz, sw_;
        sx = sy = sz = sw_ = 0.f;
        if (staged) {
            #pragma unroll
            for (int m = 0; m < 8; m++) {
                float4 v = sh4[t * 9 + m];
                sx += v.x; sy += v.y; sz += v.z; sw_ += v.w;
            }
        } else {
            const float4* lh = reinterpret_cast<const float4*>(log_h) + (size_t)i * M;
            for (int m = 0; m < M; m++) {
                float4 v = lh[m];
                sx += v.x; sy += v.y; sz += v.z; sw_ += v.w;
            }
        }
        float e0 = fminf(fmaxf(sx * inv, -50.f), 50.f);
        float e1 = fminf(fmaxf(sy * inv, -50.f), 50.f);
        float e2 = fminf(fmaxf(sz * inv, -50.f), 50.f);
        float e3 = fminf(fmaxf(sw_ * inv, -50.f), 50.f);

        float d = dur[i];
        int cause = et[i];
        float eta_own = (cause == 1) ? e0 : (cause == 2) ? e1 : (cause == 3) ? e2
                       : (cause == 4) ? e3 : 0.f;
        int b = bucket_of(d);
        int pos = atomicAdd(&g_cnt[b], 1);
        float4 pa = make_float4(d, expf(e0), expf(e1), expf(e2));
        float4 pq = make_float4(expf(e3), __int_as_float(cause), eta_own, 0.f);
        if (pos < CAPB) {
            float4* p = reinterpret_cast<float4*>(&g_elem[(size_t)b * CAPB + pos]);
            p[0] = pa; p[1] = pq;
        } else {
            int oi = atomicAdd(&g_ovf_cnt, 1);
            float4* p = reinterpret_cast<float4*>(&g_ovf[oi]);
            p[0] = pa; p[1] = pq;
            g_ovfb[oi] = b;
        }
    }
    __syncthreads();

    // ---- stage logits (coalesced) -> shared, CE with max-subtraction ----
    if (staged) {
        int nf4 = cnt * 10;
        const float4* src = reinterpret_cast<const float4*>(logits) + (size_t)blockBase * 10;
        for (int j = t; j < nf4; j += TPB) {
            int l = j / 10, r = j - l * 10;
            sh4[l * 11 + r] = src[j];
        }
    }
    __syncthreads();

    double ce = 0.0;
    if (t < cnt) {
        float lm[NCLS];
        #pragma unroll
        for (int j = 0; j < NCLS; j++) lm[j] = 0.f;
        if (staged) {
            #pragma unroll
            for (int j = 0; j < 10; j++) {
                float4 v = sh4[t * 11 + j];
                int base = j * 4;
                lm[(base + 0) % NCLS] += v.x;
                lm[(base + 1) % NCLS] += v.y;
                lm[(base + 2) % NCLS] += v.z;
                lm[(base + 3) % NCLS] += v.w;
            }
        } else {
            const float* lg = logits + (size_t)i * M * NCLS;
            for (int q = 0; q < M * NCLS; q++) lm[q % NCLS] += lg[q];
        }
        float mj[NCLS], mx = -3.4e38f;
        #pragma unroll
        for (int j = 0; j < NCLS; j++) { mj[j] = lm[j] * inv; mx = fmaxf(mx, mj[j]); }
        float se = 0.f;
        #pragma unroll
        for (int j = 0; j < NCLS; j++) se += expf(mj[j] - mx);
        ce = (double)(mx + logf(se) - mj[labels[i]]);
    }
    double v = warp_redd(ce);
    if ((t & 31) == 0 && v != 0.0) atomicAdd(&s_ce, v);
    __syncthreads();
    if (t == 0 && s_ce != 0.0) atomicAdd(&g_ce, s_ce);
}

// ---------------------------------------------------------------- bucket sums
// Float accumulation (<=64 values/bucket, rel err ~1e-7); fp64 only at the write.
// warp_redf result valid in lane 0 ONLY -> lane 0 writes ALL four causes.
__global__ void __launch_bounds__(256) k_bsum() {
    int t = threadIdx.x;
    int w = t >> 5, lane = t & 31;
    int nov = g_ovf_cnt;                       // normally 0
    for (int b = blockIdx.x * 8 + w; b < NB; b += gridDim.x * 8) {
        int m = min(g_cnt[b], CAPB);
        float a0 = 0.f, a1 = 0.f, a2 = 0.f, a3 = 0.f;
        #pragma unroll
        for (int r = 0; r < 2; r++) {
            int j = lane + r * 32;
            if (j < m) {
                const float4* p = reinterpret_cast<const float4*>(&g_elem[(size_t)b * CAPB + j]);
                float4 a = p[0], q = p[1];
                a0 += a.y; a1 += a.z; a2 += a.w; a3 += q.x;
            }
        }
        a0 = warp_redf(a0); a1 = warp_redf(a1); a2 = warp_redf(a2); a3 = warp_redf(a3);
        if (lane == 0) {
            float s[KC] = {a0, a1, a2, a3};
            for (int j = 0; j < nov; j++) {     // fold overflow (normally empty)
                if (g_ovfb[j] == b) {
                    const float4* p = reinterpret_cast<const float4*>(&g_ovf[j]);
                    float4 a = p[0], q = p[1];
                    #pragma unroll
                    for (int c = 0; c < KC; c++) s[c] += elem_f(a, q, c);
                }
            }
            #pragma unroll
            for (int c = 0; c < KC; c++) {
                double sd = (double)s[c];
                g_bsum[b * KC + c] = sd;
                atomicAdd(&g_part_sum[c * NPART + b / BPP], sd);
            }
        }
    }
}

// ---------------------------------------------------------------- suffix over parts (1 block)
__global__ void __launch_bounds__(NPART) k_sufB() {
    __shared__ double sd[NPART];
    int t = threadIdx.x;
    for (int c = 0; c < KC; c++) {
        double own = g_part_sum[c * NPART + t];
        sd[t] = own;
        __syncthreads();
        for (int off = 1; off < NPART; off <<= 1) {
            double v = (t + off < NPART) ? sd[t + off] : 0.0;
            __syncthreads();
            sd[t] += v;
            __syncthreads();
        }
        g_part_sufx[c * NPART + t] = sd[t] - own;  // exclusive suffix over parts
        __syncthreads();
    }
}

// ---------------------------------------------------------------- within-part suffix fixup
__global__ void __launch_bounds__(BPP) k_sufC() {
    __shared__ double sd[BPP];
    int t = threadIdx.x, p = blockIdx.x;
    int b = p * BPP + t;
    for (int c = 0; c < KC; c++) {
        double own = g_bsum[b * KC + c];
        sd[t] = own;
        __syncthreads();
        for (int off = 1; off < BPP; off <<= 1) {
            double v = (t + off < BPP) ? sd[t + off] : 0.0;
            __syncthreads();
            sd[t] += v;
            __syncthreads();
        }
        g_sufx[b * KC + c] = g_part_sufx[c * NPART + p] + sd[t] - own;
        __syncthreads();
    }
}

// ---------------------------------------------------------------- events (warp-per-bucket loop)
// fp32 log of the denominator (abs err ~5e-6 per term vs 1e-3 tolerance).
__global__ void __launch_bounds__(256) k_events() {
    __shared__ float  sh_dur[8][CAPB];
    __shared__ float  sh_f[8][KC][CAPB];
    __shared__ float  sh_eo[8][CAPB];
    __shared__ int    sh_c[8][CAPB];
    __shared__ double s_sum[KC];
    __shared__ double s_cnt[KC];

    int t = threadIdx.x;
    int w = t >> 5, lane = t & 31;
    if (t < KC) { s_sum[t] = 0.0; s_cnt[t] = 0.0; }
    __syncthreads();

    int nov_all = g_ovf_cnt;
    double acc_sum[KC] = {0.0, 0.0, 0.0, 0.0};
    int    acc_cnt[KC] = {0, 0, 0, 0};

    for (int b = blockIdx.x * 8 + w; b < NB; b += gridDim.x * 8) {
        int cnt = g_cnt[b];
        int m = min(cnt, CAPB);
        if (m == 0) continue;
        int nov = (cnt > CAPB) ? nov_all : 0;

        for (int j = lane; j < m; j += 32) {
            const float4* p = reinterpret_cast<const float4*>(&g_elem[(size_t)b * CAPB + j]);
            float4 a = p[0], q = p[1];
            sh_dur[w][j]  = a.x;
            sh_f[w][0][j] = a.y;
            sh_f[w][1][j] = a.z;
            sh_f[w][2][j] = a.w;
            sh_f[w][3][j] = q.x;
            sh_eo[w][j]   = q.z;
            sh_c[w][j]    = __float_as_int(q.y);
        }
        __syncwarp();

        #pragma unroll
        for (int r = 0; r < 2; r++) {
            int j = lane + r * 32;
            if (j < m) {
                int cv = sh_c[w][j];
                if (cv > 0) {
                    int cc = cv - 1;
                    float d_e = sh_dur[w][j];
                    const float* fp = sh_f[w][cc];
                    float acc = 0.f;
                    for (int j2 = 0; j2 < m; j2++)
                        acc += (sh_dur[w][j2] >= d_e) ? fp[j2] : 0.f;
                    for (int j2 = 0; j2 < nov; j2++) {   // same-bucket overflow elems
                        if (g_ovfb[j2] == b) {
                            const float4* p = reinterpret_cast<const float4*>(&g_ovf[j2]);
                            float4 a = p[0], q = p[1];
                            acc += (a.x >= d_e) ? elem_f(a, q, cc) : 0.f;
                        }
                    }
                    float denom = (float)g_sufx[b * KC + cc] + acc;
                    acc_sum[cc] += (double)(sh_eo[w][j] - logf(denom + 1e-8f));
                    acc_cnt[cc] += 1;
                }
            }
        }
        __syncwarp();
    }

    #pragma unroll
    for (int c = 0; c < KC; c++) {
        double v = warp_redd(acc_sum[c]);
        double k = warp_redd((double)acc_cnt[c]);
        if (lane == 0 && k != 0.0) {
            atomicAdd(&s_sum[c], v);
            atomicAdd(&s_cnt[c], k);
        }
    }
    __syncthreads();
    if (t < KC && s_cnt[t] != 0.0) {
        atomicAdd(&g_evsum[t], s_sum[t]);
        atomicAdd(&g_evcnt[t], s_cnt[t]);
    }
}

// ---------------------------------------------------------------- finalize (+ overflow events)
__global__ void k_fin(float* __restrict__ out, int n) {
    double esum[KC], ecnt[KC];
    #pragma unroll
    for (int c = 0; c < KC; c++) { esum[c] = g_evsum[c]; ecnt[c] = g_evcnt[c]; }

    int nov = g_ovf_cnt;  // normally 0
    for (int i = 0; i < nov; i++) {
        const float4* p = reinterpret_cast<const float4*>(&g_ovf[i]);
        float4 a = p[0], q = p[1];
        int cv = __float_as_int(q.y);
        if (cv <= 0) continue;
        int cc = cv - 1, b = g_ovfb[i];
        float d_e = a.x;
        float acc = 0.f;
        int m = min(g_cnt[b], CAPB);
        for (int j = 0; j < m; j++) {
            const float4* pj = reinterpret_cast<const float4*>(&g_elem[(size_t)b * CAPB + j]);
            float4 aj = pj[0], qj = pj[1];
            acc += (aj.x >= d_e) ? elem_f(aj, qj, cc) : 0.f;
        }
        for (int j = 0; j < nov; j++) {
            if (g_ovfb[j] == b) {
                const float4* pj = reinterpret_cast<const float4*>(&g_ovf[j]);
                float4 aj = pj[0], qj = pj[1];
                acc += (aj.x >= d_e) ? elem_f(aj, qj, cc) : 0.f;
            }
        }
        float denom = (float)g_sufx[b * KC + cc] + acc;
        esum[cc] += (double)(q.z - logf(denom + 1e-8f));
        ecnt[cc] += 1.0;
    }

    double ls = 0.0;
    #pragma unroll
    for (int c = 0; c < KC; c++) ls += -esum[c] / (ecnt[c] + EPS);
    double lc = g_ce / (double)n;
    out[0] = (float)(ALPHA * ls + (1.0 - ALPHA) * lc);
}

// ---------------------------------------------------------------- launch
extern "C" void kernel_launch(void* const* d_in, const int* in_sizes, int n_in,
                              void* d_out, int out_size) {
    const float* log_h  = (const float*)d_in[0];
    const float* logits = (const float*)d_in[1];
    const float* dur    = (const float*)d_in[2];
    const int*   et     = (const int*)d_in[3];
    const int*   labels = (const int*)d_in[4];
    float* out = (float*)d_out;

    int n = in_sizes[2];
    int M = in_sizes[0] / (n * KC);

    int nb = (n + TPB - 1) / TPB;

    k_init<<<(NB + TPB - 1) / TPB, TPB>>>();
    k_nop<<<1, 32>>>();                         // spacer: ncu #4 = k_bsum
    k_passA<<<nb, TPB>>>(log_h, logits, dur, et, labels, n, M);
    k_bsum<<<512, 256>>>();
    k_sufB<<<1, NPART>>>();
    k_sufC<<<NPART, BPP>>>();
    k_events<<<512, 256>>>();
    k_fin<<<1, 1>>>(out, n);
}